// round 3
// baseline (speedup 1.0000x reference)
#include <cuda_runtime.h>
#include <cstdint>
#include <float.h>

#define BB 16
#define NN 2048
#define CC 80

// ---------------- scratch (device globals; no allocations) ----------------
__device__ float4             g_xyxy [BB * NN];
__device__ float              g_obj  [BB * NN];
__device__ float              g_conf [BB * NN];
__device__ int                g_cls  [BB * NN];
__device__ unsigned long long g_key64[BB * NN];

// ---------------- kernel 1: per-element prep (one THREAD per element) -----
__global__ __launch_bounds__(128) void prep_kernel(const float* __restrict__ boxes,
                                                   const float* __restrict__ objn,
                                                   const float* __restrict__ logits,
                                                   float* __restrict__ out)
{
    int gw = blockIdx.x * blockDim.x + threadIdx.x;   // element index
    if (gw >= BB * NN) return;

    // argmax / max over 80 logits, float4 loads, ascending order (stable argmax)
    const float4* lg4 = (const float4*)(logits + (size_t)gw * CC);
    float v = -FLT_MAX;
    int   vi = 0;
    #pragma unroll
    for (int q = 0; q < CC / 4; q++) {
        float4 x = lg4[q];
        int k = q * 4;
        if (x.x > v) { v = x.x; vi = k;     }
        if (x.y > v) { v = x.y; vi = k + 1; }
        if (x.z > v) { v = x.z; vi = k + 2; }
        if (x.w > v) { v = x.w; vi = k + 3; }
    }

    float ob = objn[gw];
    float4 bx = ((const float4*)boxes)[gw];
    float4 xy;
    xy.x = bx.x - bx.z * 0.5f;
    xy.y = bx.y - bx.w * 0.5f;
    xy.z = bx.x + bx.z * 0.5f;
    xy.w = bx.y + bx.w * 0.5f;
    bool valid = ob > 0.5f;

    // packed stable-descending sort key
    unsigned u = __float_as_uint(valid ? ob : -1.0f);
    u = (u & 0x80000000u) ? ~u : (u | 0x80000000u);
    unsigned idx = (unsigned)(gw & (NN - 1));
    g_key64[gw] = ((unsigned long long)u << 32) | (0xFFFFFFFFu - idx);

    g_xyxy[gw] = xy;
    g_obj [gw] = ob;
    g_conf[gw] = v;
    g_cls [gw] = vi;

    // zero-init output row (batch index in col 0)
    int b = gw / NN;
    float4* row = (float4*)(out + (size_t)gw * 8);
    row[0] = make_float4((float)b, 0.f, 0.f, 0.f);
    row[1] = make_float4(0.f, 0.f, 0.f, 0.f);
}

// ---------------- fused kernel 2: per-batch sort + class NMS + output -----
struct SmemLayout {
    unsigned long long s[NN];       // sort keys
    float4             boxes[NN];   // sorted xyxy
    int                cls[NN];     // sorted class
    unsigned short     idx[NN];     // sorted -> original index
    unsigned short     list[NN];    // per-class member lists (sorted positions)
    unsigned char      alive[NN];
    int                counts[CC];
    int                offs[CC];
    int                M;
};

#define NWARPS 32   // 1024 threads

__device__ __forceinline__ void reg_cmpex(unsigned long long& r, int p, int k, int j)
{
    unsigned long long o = __shfl_xor_sync(0xFFFFFFFFu, r, j);
    bool lower   = ((p & j) == 0);
    bool desc    = ((p & k) == 0);
    bool takeMax = (lower == desc);
    unsigned long long mx = r > o ? r : o;
    unsigned long long mn = r > o ? o : r;
    r = takeMax ? mx : mn;
}

__global__ __launch_bounds__(1024) void fused_kernel(float* __restrict__ out)
{
    extern __shared__ char raw[];
    SmemLayout* sm = (SmemLayout*)raw;
    int b    = blockIdx.x;
    int t    = threadIdx.x;
    int warp = t >> 5;
    int lane = t & 31;

    // ---- load keys ----
    sm->s[t]        = g_key64[b * NN + t];
    sm->s[t + 1024] = g_key64[b * NN + t + 1024];
    if (t == 0) sm->M = 0;
    __syncthreads();

    // ---- hybrid bitonic sort (descending on u64 => stable-desc on key) ----
    unsigned long long r0, r1;
    // phases k=2..32: fully in registers (all j<=16)
    r0 = sm->s[t]; r1 = sm->s[t + 1024];
    #pragma unroll
    for (int k = 2; k <= 32; k <<= 1) {
        #pragma unroll
        for (int j = k >> 1; j > 0; j >>= 1) {
            reg_cmpex(r0, t, k, j);
            reg_cmpex(r1, t + 1024, k, j);
        }
    }
    sm->s[t] = r0; sm->s[t + 1024] = r1;
    __syncthreads();

    // phases k=64..2048: smem rounds for j>=32, register rounds for j<=16
    #pragma unroll
    for (int k = 64; k <= NN; k <<= 1) {
        for (int j = k >> 1; j >= 32; j >>= 1) {
            #pragma unroll
            for (int rr = 0; rr < 2; rr++) {
                int idx = t + rr * 1024;
                int ixj = idx ^ j;
                if (ixj > idx) {
                    unsigned long long a = sm->s[idx], c = sm->s[ixj];
                    bool desc = ((idx & k) == 0);
                    if (desc ? (a < c) : (a > c)) { sm->s[idx] = c; sm->s[ixj] = a; }
                }
            }
            __syncthreads();
        }
        r0 = sm->s[t]; r1 = sm->s[t + 1024];
        #pragma unroll
        for (int j = 16; j > 0; j >>= 1) {
            reg_cmpex(r0, t, k, j);
            reg_cmpex(r1, t + 1024, k, j);
        }
        sm->s[t] = r0; sm->s[t + 1024] = r1;
        __syncthreads();
    }

    // ---- valid count M (boundary of keys > 0) ----
    #pragma unroll
    for (int rr = 0; rr < 2; rr++) {
        int p = t + rr * 1024;
        unsigned hi = (unsigned)(sm->s[p] >> 32);
        bool valid = hi > 0x80000000u;
        if (valid) {
            bool nextInvalid = (p == NN - 1) ||
                               ((unsigned)(sm->s[p + 1] >> 32) <= 0x80000000u);
            if (nextInvalid) sm->M = p + 1;
        }
    }
    __syncthreads();
    int M = sm->M;

    // ---- gather sorted attributes into smem (valid prefix only) ----
    #pragma unroll
    for (int rr = 0; rr < 2; rr++) {
        int p = t + rr * 1024;
        if (p < M) {
            unsigned n = 0xFFFFFFFFu - (unsigned)(sm->s[p] & 0xFFFFFFFFu);
            int g = b * NN + (int)n;
            sm->boxes[p] = g_xyxy[g];
            sm->cls[p]   = g_cls[g];
            sm->idx[p]   = (unsigned short)n;
        }
    }
    __syncthreads();

    // ---- per-class counts (warp w handles classes w, w+32, w+64) ----
    for (int c = warp; c < CC; c += NWARPS) {
        int cnt = 0;
        for (int base = 0; base < M; base += 32) {
            int p = base + lane;
            bool match = (p < M) && (sm->cls[p] == c);
            cnt += __popc(__ballot_sync(0xFFFFFFFFu, match));
        }
        if (lane == 0) sm->counts[c] = cnt;
    }
    __syncthreads();

    // ---- exclusive scan of 80 counts (warp 0) ----
    if (t < 32) {
        int v0 = sm->counts[t];
        int v1 = sm->counts[t + 32];
        int v2 = (t < CC - 64) ? sm->counts[t + 64] : 0;
        int s0 = v0, s1 = v1, s2 = v2;
        #pragma unroll
        for (int o = 1; o < 32; o <<= 1) {
            int a0 = __shfl_up_sync(0xFFFFFFFFu, s0, o);
            int a1 = __shfl_up_sync(0xFFFFFFFFu, s1, o);
            int a2 = __shfl_up_sync(0xFFFFFFFFu, s2, o);
            if (lane >= o) { s0 += a0; s1 += a1; s2 += a2; }
        }
        int tot0 = __shfl_sync(0xFFFFFFFFu, s0, 31);
        s1 += tot0;
        int tot1 = __shfl_sync(0xFFFFFFFFu, s1, 31);
        s2 += tot1;
        sm->offs[t]      = s0 - v0;
        sm->offs[t + 32] = s1 - v1;
        if (t < CC - 64) sm->offs[t + 64] = s2 - v2;
    }
    __syncthreads();

    // ---- scatter class member lists (stable, ascending sorted position) ----
    for (int c = warp; c < CC; c += NWARPS) {
        int off = sm->offs[c];
        int k2 = 0;
        for (int base = 0; base < M; base += 32) {
            int p = base + lane;
            bool match = (p < M) && (sm->cls[p] == c);
            unsigned mask = __ballot_sync(0xFFFFFFFFu, match);
            if (match) {
                int d = off + k2 + __popc(mask & ((1u << lane) - 1u));
                sm->list[d]  = (unsigned short)p;
                sm->alive[d] = 1;
            }
            k2 += __popc(mask);
        }
    }
    __syncwarp();

    // ---- warp-local greedy NMS per class + output write ----
    for (int c = warp; c < CC; c += NWARPS) {
        int K   = sm->counts[c];
        int off = sm->offs[c];

        for (int i = 0; i < K - 1; i++) {
            if (sm->alive[off + i]) {
                float4 bi = sm->boxes[sm->list[off + i]];
                float areaI = (bi.z - bi.x + 1.0f) * (bi.w - bi.y + 1.0f);
                for (int j = i + 1 + lane; j < K; j += 32) {
                    if (sm->alive[off + j]) {
                        float4 bj = sm->boxes[sm->list[off + j]];
                        float x1 = fmaxf(bi.x, bj.x);
                        float y1 = fmaxf(bi.y, bj.y);
                        float x2 = fminf(bi.z, bj.z);
                        float y2 = fminf(bi.w, bj.w);
                        float iw = fmaxf(x2 - x1 + 1.0f, 0.0f);
                        float ih = fmaxf(y2 - y1 + 1.0f, 0.0f);
                        float inter = iw * ih;
                        float areaJ = (bj.z - bj.x + 1.0f) * (bj.w - bj.y + 1.0f);
                        float iou = inter / (areaI + areaJ - inter);
                        if (iou >= 0.5f) sm->alive[off + j] = 0;
                    }
                }
            }
            __syncwarp();
        }

        for (int k2 = lane; k2 < K; k2 += 32) {
            if (sm->alive[off + k2]) {
                int p = sm->list[off + k2];
                int n = sm->idx[p];
                float4 bx = sm->boxes[p];
                float ob = g_obj [b * NN + n];
                float cf = g_conf[b * NN + n];
                float4* row = (float4*)(out + ((size_t)(b * NN + p)) * 8);
                row[0] = make_float4((float)b, bx.x, bx.y, bx.z);
                row[1] = make_float4(bx.w, ob, cf, (float)c);
            }
        }
        __syncwarp();
    }
}

// ---------------- launch ---------------------------------------------------
extern "C" void kernel_launch(void* const* d_in, const int* in_sizes, int n_in,
                              void* d_out, int out_size)
{
    const float* boxes  = nullptr;
    const float* objn   = nullptr;
    const float* logits = nullptr;
    for (int i = 0; i < n_in; i++) {
        if      (in_sizes[i] == BB * NN * 4)  boxes  = (const float*)d_in[i];
        else if (in_sizes[i] == BB * NN)      objn   = (const float*)d_in[i];
        else if (in_sizes[i] == BB * NN * CC) logits = (const float*)d_in[i];
    }
    float* out = (float*)d_out;

    int threads = 128;
    int blocks  = (BB * NN + threads - 1) / threads;
    prep_kernel<<<blocks, threads>>>(boxes, objn, logits, out);

    size_t smem = sizeof(SmemLayout);
    cudaFuncSetAttribute(fused_kernel, cudaFuncAttributeMaxDynamicSharedMemorySize,
                         (int)smem);
    fused_kernel<<<BB, 1024, smem>>>(out);
}

// round 4
// speedup vs baseline: 1.6175x; 1.6175x over previous
#include <cuda_runtime.h>
#include <cstdint>
#include <float.h>

#define BB 16
#define NN 2048
#define CC 80
#define NBK 2048          // key buckets (mantissa bits [22:12])

// ---------------- scratch (device globals; no allocations) ----------------
__device__ float4             g_xyxy [BB * NN];
__device__ float              g_obj  [BB * NN];
__device__ float              g_conf [BB * NN];
__device__ int                g_cls  [BB * NN];
__device__ unsigned long long g_key64[BB * NN];

__device__ float4             g_xyxy_s[BB * NN];
__device__ float              g_obj_s [BB * NN];
__device__ float              g_conf_s[BB * NN];
__device__ unsigned char      g_cls_s [BB * NN];
__device__ int                g_M[BB];

// ---------------- kernel 1: per-element prep (one THREAD per element) -----
__global__ __launch_bounds__(128) void prep_kernel(const float* __restrict__ boxes,
                                                   const float* __restrict__ objn,
                                                   const float* __restrict__ logits,
                                                   float* __restrict__ out)
{
    int gw = blockIdx.x * blockDim.x + threadIdx.x;
    if (gw >= BB * NN) return;

    const float4* lg4 = (const float4*)(logits + (size_t)gw * CC);
    float v = -FLT_MAX;
    int   vi = 0;
    #pragma unroll
    for (int q = 0; q < CC / 4; q++) {
        float4 x = lg4[q];
        int k = q * 4;
        if (x.x > v) { v = x.x; vi = k;     }
        if (x.y > v) { v = x.y; vi = k + 1; }
        if (x.z > v) { v = x.z; vi = k + 2; }
        if (x.w > v) { v = x.w; vi = k + 3; }
    }

    float ob = objn[gw];
    float4 bx = ((const float4*)boxes)[gw];
    float4 xy;
    xy.x = bx.x - bx.z * 0.5f;
    xy.y = bx.y - bx.w * 0.5f;
    xy.z = bx.x + bx.z * 0.5f;
    xy.w = bx.y + bx.w * 0.5f;
    bool valid = ob > 0.5f;

    unsigned u = __float_as_uint(valid ? ob : -1.0f);
    u = (u & 0x80000000u) ? ~u : (u | 0x80000000u);
    unsigned idx = (unsigned)(gw & (NN - 1));
    g_key64[gw] = ((unsigned long long)u << 32) | (0xFFFFFFFFu - idx);

    g_xyxy[gw] = xy;
    g_obj [gw] = ob;
    g_conf[gw] = v;
    g_cls [gw] = vi;

    int b = gw / NN;
    float4* row = (float4*)(out + (size_t)gw * 8);
    row[0] = make_float4((float)b, 0.f, 0.f, 0.f);
    row[1] = make_float4(0.f, 0.f, 0.f, 0.f);
}

// ---------------- kernel 2: per-batch counting sort of valid elements ----
// valid obj in (0.5, 1) -> exponent 126 -> bucket = mantissa[22:12], monotone.
__global__ __launch_bounds__(1024) void rank_kernel()
{
    __shared__ int                hist[NBK];   // counts, then scatter cursors
    __shared__ int                offs[NBK];   // descending-order start offsets
    __shared__ unsigned long long skey[NN];    // scattered keys (sorted at end)
    __shared__ int                wsum[32];
    __shared__ int                Msh;

    int b = blockIdx.x;
    int t = threadIdx.x;
    int lane = t & 31, warp = t >> 5;

    hist[t] = 0; hist[t + 1024] = 0;
    __syncthreads();

    unsigned long long k0 = g_key64[b * NN + t];
    unsigned long long k1 = g_key64[b * NN + t + 1024];
    bool v0 = (unsigned)(k0 >> 32) > 0x80000000u;
    bool v1 = (unsigned)(k1 >> 32) > 0x80000000u;
    int bk0 = (int)((k0 >> 44) & (NBK - 1));
    int bk1 = (int)((k1 >> 44) & (NBK - 1));
    if (v0) atomicAdd(&hist[bk0], 1);
    if (v1) atomicAdd(&hist[bk1], 1);
    __syncthreads();

    // exclusive scan over DESCENDING bucket order (largest key first)
    int c0 = hist[NBK - 1 - 2 * t];
    int c1 = hist[NBK - 2 - 2 * t];
    int sum = c0 + c1;
    int inc = sum;
    #pragma unroll
    for (int o = 1; o < 32; o <<= 1) {
        int a = __shfl_up_sync(0xFFFFFFFFu, inc, o);
        if (lane >= o) inc += a;
    }
    if (lane == 31) wsum[warp] = inc;
    __syncthreads();
    if (warp == 0) {
        int wv = wsum[lane];
        int winc = wv;
        #pragma unroll
        for (int o = 1; o < 32; o <<= 1) {
            int a = __shfl_up_sync(0xFFFFFFFFu, winc, o);
            if (lane >= o) winc += a;
        }
        wsum[lane] = winc - wv;   // exclusive warp offsets
    }
    __syncthreads();
    int excl = wsum[warp] + (inc - sum);
    offs[NBK - 1 - 2 * t] = excl;
    offs[NBK - 2 - 2 * t] = excl + c0;
    if (t == 1023) Msh = excl + sum;   // total valid count
    __syncthreads();

    // cursors = offs, then scatter keys into bucket slots
    hist[t] = offs[t];
    hist[t + 1024] = offs[t + 1024];
    __syncthreads();
    if (v0) { int s = atomicAdd(&hist[bk0], 1); skey[s] = k0; }
    if (v1) { int s = atomicAdd(&hist[bk1], 1); skey[s] = k1; }
    __syncthreads();

    // per-bucket insertion sort, descending u64 (stability via idx in low bits)
    #pragma unroll
    for (int rr = 0; rr < 2; rr++) {
        int bk = t + rr * 1024;
        int s = offs[bk], e = hist[bk];
        for (int i = s + 1; i < e; i++) {
            unsigned long long key = skey[i];
            int j = i - 1;
            while (j >= s && skey[j] < key) { skey[j + 1] = skey[j]; j--; }
            skey[j + 1] = key;
        }
    }
    __syncthreads();

    // gather sorted attributes to global
    int M = Msh;
    #pragma unroll
    for (int rr = 0; rr < 2; rr++) {
        int p = t + rr * 1024;
        if (p < M) {
            unsigned n = 0xFFFFFFFFu - (unsigned)(skey[p] & 0xFFFFFFFFu);
            int g = b * NN + (int)n;
            int d = b * NN + p;
            g_xyxy_s[d] = g_xyxy[g];
            g_obj_s [d] = g_obj [g];
            g_conf_s[d] = g_conf[g];
            g_cls_s [d] = (unsigned char)g_cls[g];
        }
    }
    if (t == 0) g_M[b] = M;
}

// ---------------- kernel 3: per-(batch,class) greedy NMS + output --------
#define NMS_WARPS 4
#define LCAP 128
__global__ __launch_bounds__(NMS_WARPS * 32) void nms_kernel(float* __restrict__ out)
{
    __shared__ unsigned short list_s [NMS_WARPS][LCAP];
    __shared__ unsigned char  alive_s[NMS_WARPS][LCAP];

    int warp = threadIdx.x >> 5;
    int lane = threadIdx.x & 31;
    int w = blockIdx.x * NMS_WARPS + warp;
    if (w >= BB * CC) return;
    int b = w / CC;
    int c = w % CC;

    int M = g_M[b];
    const unsigned char* cls = g_cls_s + b * NN;
    unsigned short* list  = list_s [warp];
    unsigned char*  alive = alive_s[warp];

    // ordered ballot-compaction of class members within the valid prefix
    int K = 0;
    for (int base = 0; base < M; base += 32) {
        int p = base + lane;
        bool match = (p < M) && (cls[p] == (unsigned char)c);
        unsigned mask = __ballot_sync(0xFFFFFFFFu, match);
        if (match) {
            int d = K + __popc(mask & ((1u << lane) - 1u));
            if (d < LCAP) list[d] = (unsigned short)p;
        }
        K += __popc(mask);
    }
    if (K > LCAP) K = LCAP;
    for (int k2 = lane; k2 < K; k2 += 32) alive[k2] = 1;
    __syncwarp();

    const float4* boxes = g_xyxy_s + b * NN;

    for (int i = 0; i < K - 1; i++) {
        if (alive[i]) {
            float4 bi = boxes[list[i]];
            float areaI = (bi.z - bi.x + 1.0f) * (bi.w - bi.y + 1.0f);
            for (int j = i + 1 + lane; j < K; j += 32) {
                if (alive[j]) {
                    float4 bj = boxes[list[j]];
                    float x1 = fmaxf(bi.x, bj.x);
                    float y1 = fmaxf(bi.y, bj.y);
                    float x2 = fminf(bi.z, bj.z);
                    float y2 = fminf(bi.w, bj.w);
                    float iw = fmaxf(x2 - x1 + 1.0f, 0.0f);
                    float ih = fmaxf(y2 - y1 + 1.0f, 0.0f);
                    float inter = iw * ih;
                    float areaJ = (bj.z - bj.x + 1.0f) * (bj.w - bj.y + 1.0f);
                    float iou = inter / (areaI + areaJ - inter);
                    if (iou >= 0.5f) alive[j] = 0;
                }
            }
        }
        __syncwarp();
    }

    for (int k2 = lane; k2 < K; k2 += 32) {
        if (alive[k2]) {
            int p = list[k2];
            float4 bx = boxes[p];
            float4* row = (float4*)(out + ((size_t)(b * NN + p)) * 8);
            row[0] = make_float4((float)b, bx.x, bx.y, bx.z);
            row[1] = make_float4(bx.w, g_obj_s[b * NN + p],
                                 g_conf_s[b * NN + p], (float)c);
        }
    }
}

// ---------------- launch ---------------------------------------------------
extern "C" void kernel_launch(void* const* d_in, const int* in_sizes, int n_in,
                              void* d_out, int out_size)
{
    const float* boxes  = nullptr;
    const float* objn   = nullptr;
    const float* logits = nullptr;
    for (int i = 0; i < n_in; i++) {
        if      (in_sizes[i] == BB * NN * 4)  boxes  = (const float*)d_in[i];
        else if (in_sizes[i] == BB * NN)      objn   = (const float*)d_in[i];
        else if (in_sizes[i] == BB * NN * CC) logits = (const float*)d_in[i];
    }
    float* out = (float*)d_out;

    prep_kernel<<<(BB * NN + 127) / 128, 128>>>(boxes, objn, logits, out);
    rank_kernel<<<BB, 1024>>>();
    nms_kernel<<<(BB * CC + NMS_WARPS - 1) / NMS_WARPS, NMS_WARPS * 32>>>(out);
}